// round 1
// baseline (speedup 1.0000x reference)
#include <cuda_runtime.h>

#define BB 4
#define SS 2048
#define DD 512
#define HH 8
#define DKK 64
#define MM (BB*SS)

// Scratch (allocations are forbidden; __device__ globals are the sanctioned path)
__device__ float g_Q[BB*HH*SS*DKK];   // [B,H,S,dk]
__device__ float g_K[BB*HH*SS*DKK];
__device__ float g_V[BB*HH*SS*DKK];
__device__ float g_C[BB*SS*DD];       // context [B,S,D]

// ---------------------------------------------------------------------------
// GEMM (NT): C[m,n] = sum_k A[m,k] * W[n,k].  M=8192, N=512, K=512.
// 128x128 tile, BK=8, 256 threads, 8x8 per-thread micro-tile.
// ---------------------------------------------------------------------------
__global__ __launch_bounds__(256, 2)
void proj_gemm(const float* __restrict__ X, const float* __restrict__ W, int which)
{
    __shared__ float As[8][128];
    __shared__ float Bs[8][128];

    float* outp = (which == 0) ? g_Q : (which == 1) ? g_K : g_V;

    const int tid = threadIdx.x;
    const int bm  = blockIdx.x * 128;
    const int bn  = blockIdx.y * 128;
    const int lr  = tid >> 1;           // 0..127 : tile row loaded by this thread
    const int lk  = (tid & 1) << 2;     // 0 or 4 : k offset
    const int tx  = tid & 15;           // n micro-tile
    const int ty  = tid >> 4;           // m micro-tile

    float acc[8][8];
    #pragma unroll
    for (int i = 0; i < 8; i++)
        #pragma unroll
        for (int j = 0; j < 8; j++) acc[i][j] = 0.f;

    const float* Ap = X + (size_t)(bm + lr) * DD + lk;
    const float* Bp = W + (size_t)(bn + lr) * DD + lk;

    for (int k0 = 0; k0 < DD; k0 += 8) {
        float4 av = *(const float4*)(Ap + k0);
        float4 bv = *(const float4*)(Bp + k0);
        __syncthreads();
        As[lk+0][lr]=av.x; As[lk+1][lr]=av.y; As[lk+2][lr]=av.z; As[lk+3][lr]=av.w;
        Bs[lk+0][lr]=bv.x; Bs[lk+1][lr]=bv.y; Bs[lk+2][lr]=bv.z; Bs[lk+3][lr]=bv.w;
        __syncthreads();
        #pragma unroll
        for (int kk = 0; kk < 8; kk++) {
            float4 a0 = *(const float4*)&As[kk][ty*8];
            float4 a1 = *(const float4*)&As[kk][ty*8+4];
            float4 b0 = *(const float4*)&Bs[kk][tx*8];
            float4 b1 = *(const float4*)&Bs[kk][tx*8+4];
            float ar[8] = {a0.x,a0.y,a0.z,a0.w,a1.x,a1.y,a1.z,a1.w};
            float br[8] = {b0.x,b0.y,b0.z,b0.w,b1.x,b1.y,b1.z,b1.w};
            #pragma unroll
            for (int i = 0; i < 8; i++)
                #pragma unroll
                for (int j = 0; j < 8; j++)
                    acc[i][j] = fmaf(ar[i], br[j], acc[i][j]);
        }
    }

    // Epilogue: scatter into [B,H,S,dk] layout.  n blocks of 4 never straddle a head.
    #pragma unroll
    for (int i = 0; i < 8; i++) {
        int m = bm + ty*8 + i;
        int b = m >> 11, s = m & (SS-1);
        #pragma unroll
        for (int j = 0; j < 8; j += 4) {
            int n = bn + tx*8 + j;
            int h = n >> 6, dj = n & 63;
            float4 v = make_float4(acc[i][j], acc[i][j+1], acc[i][j+2], acc[i][j+3]);
            *(float4*)&outp[((size_t)(b*HH + h)*SS + s)*DKK + dj] = v;
        }
    }
}

__global__ __launch_bounds__(256, 2)
void out_gemm(const float* __restrict__ W, float* __restrict__ out)
{
    __shared__ float As[8][128];
    __shared__ float Bs[8][128];

    const int tid = threadIdx.x;
    const int bm  = blockIdx.x * 128;
    const int bn  = blockIdx.y * 128;
    const int lr  = tid >> 1;
    const int lk  = (tid & 1) << 2;
    const int tx  = tid & 15;
    const int ty  = tid >> 4;

    float acc[8][8];
    #pragma unroll
    for (int i = 0; i < 8; i++)
        #pragma unroll
        for (int j = 0; j < 8; j++) acc[i][j] = 0.f;

    const float* Ap = g_C + (size_t)(bm + lr) * DD + lk;
    const float* Bp = W   + (size_t)(bn + lr) * DD + lk;

    for (int k0 = 0; k0 < DD; k0 += 8) {
        float4 av = *(const float4*)(Ap + k0);
        float4 bv = *(const float4*)(Bp + k0);
        __syncthreads();
        As[lk+0][lr]=av.x; As[lk+1][lr]=av.y; As[lk+2][lr]=av.z; As[lk+3][lr]=av.w;
        Bs[lk+0][lr]=bv.x; Bs[lk+1][lr]=bv.y; Bs[lk+2][lr]=bv.z; Bs[lk+3][lr]=bv.w;
        __syncthreads();
        #pragma unroll
        for (int kk = 0; kk < 8; kk++) {
            float4 a0 = *(const float4*)&As[kk][ty*8];
            float4 a1 = *(const float4*)&As[kk][ty*8+4];
            float4 b0 = *(const float4*)&Bs[kk][tx*8];
            float4 b1 = *(const float4*)&Bs[kk][tx*8+4];
            float ar[8] = {a0.x,a0.y,a0.z,a0.w,a1.x,a1.y,a1.z,a1.w};
            float br[8] = {b0.x,b0.y,b0.z,b0.w,b1.x,b1.y,b1.z,b1.w};
            #pragma unroll
            for (int i = 0; i < 8; i++)
                #pragma unroll
                for (int j = 0; j < 8; j++)
                    acc[i][j] = fmaf(ar[i], br[j], acc[i][j]);
        }
    }

    #pragma unroll
    for (int i = 0; i < 8; i++) {
        int m = bm + ty*8 + i;
        #pragma unroll
        for (int j = 0; j < 8; j += 4) {
            int n = bn + tx*8 + j;
            float4 v = make_float4(acc[i][j], acc[i][j+1], acc[i][j+2], acc[i][j+3]);
            *(float4*)&out[(size_t)m*DD + n] = v;
        }
    }
}

// ---------------------------------------------------------------------------
// Causal flash attention: 64x64 tiles, 256 threads, 4x4 per-thread micro-tile.
// K stored d-major with XOR swizzle; P reuses K's buffer.  Exactly 48KB smem.
// ---------------------------------------------------------------------------
#define SWZK(d) ((((d) >> 2) & 15) << 2)   // swizzle for d-major K
#define SWZP(r) (((r) & 15) << 2)          // swizzle for P rows

__global__ __launch_bounds__(256, 2)
void attn_kernel()
{
    __shared__ float Qs[64*64];    // row-major [q][d], pre-scaled
    __shared__ float KPs[64*64];   // K tile d-major swizzled; reused as P tile
    __shared__ float Vs[64*64];    // row-major [k][d]

    const int tid = threadIdx.x;
    const int tx  = tid & 15;      // k-cols / d-cols (4 each)
    const int ty  = tid >> 4;      // q-rows (4 each)

    const int qt = (int)gridDim.x - 1 - (int)blockIdx.x;  // long blocks launch first
    const int bh = blockIdx.y;                            // b*H + h

    const float* Qg = g_Q + (size_t)bh * SS * DKK;
    const float* Kg = g_K + (size_t)bh * SS * DKK;
    const float* Vg = g_V + (size_t)bh * SS * DKK;

    // Load Q tile (pre-scaled by 1/sqrt(dk) = 0.125)
    #pragma unroll
    for (int it = 0; it < 4; it++) {
        int idx = it*256 + tid;          // float4 index 0..1023
        int r   = idx >> 4;
        int c4  = (idx & 15) << 2;
        float4 v = *(const float4*)(Qg + (size_t)(qt*64 + r)*DKK + c4);
        v.x *= 0.125f; v.y *= 0.125f; v.z *= 0.125f; v.w *= 0.125f;
        *(float4*)&Qs[r*64 + c4] = v;
    }

    float m_i[4], l_i[4], o[4][4];
    #pragma unroll
    for (int i = 0; i < 4; i++) {
        m_i[i] = -1e30f; l_i[i] = 0.f;
        #pragma unroll
        for (int j = 0; j < 4; j++) o[i][j] = 0.f;
    }

    for (int kt = 0; kt <= qt; kt++) {
        __syncthreads();  // prev iteration done reading KPs/Vs (also covers Qs on kt=0)
        // Load K (transposed to d-major, swizzled) and V tiles
        #pragma unroll
        for (int it = 0; it < 4; it++) {
            int idx = it*256 + tid;
            int r   = idx >> 4;
            int c4  = (idx & 15) << 2;
            float4 kv = *(const float4*)(Kg + (size_t)(kt*64 + r)*DKK + c4);
            KPs[(c4+0)*64 + (r ^ SWZK(c4+0))] = kv.x;
            KPs[(c4+1)*64 + (r ^ SWZK(c4+1))] = kv.y;
            KPs[(c4+2)*64 + (r ^ SWZK(c4+2))] = kv.z;
            KPs[(c4+3)*64 + (r ^ SWZK(c4+3))] = kv.w;
            float4 vv = *(const float4*)(Vg + (size_t)(kt*64 + r)*DKK + c4);
            *(float4*)&Vs[r*64 + c4] = vv;
        }
        __syncthreads();

        // S = Q K^T  (already scaled)
        float s[4][4];
        #pragma unroll
        for (int i = 0; i < 4; i++)
            #pragma unroll
            for (int j = 0; j < 4; j++) s[i][j] = 0.f;

        #pragma unroll 8
        for (int d = 0; d < 64; d++) {
            float4 kv = *(const float4*)&KPs[d*64 + ((tx<<2) ^ SWZK(d))];
            #pragma unroll
            for (int i = 0; i < 4; i++) {
                float q = Qs[(ty*4+i)*64 + d];
                s[i][0] = fmaf(q, kv.x, s[i][0]);
                s[i][1] = fmaf(q, kv.y, s[i][1]);
                s[i][2] = fmaf(q, kv.z, s[i][2]);
                s[i][3] = fmaf(q, kv.w, s[i][3]);
            }
        }

        // Causal mask: only the diagonal tile straddles the boundary
        if (kt == qt) {
            #pragma unroll
            for (int i = 0; i < 4; i++)
                #pragma unroll
                for (int j = 0; j < 4; j++)
                    if (tx*4 + j > ty*4 + i) s[i][j] = -1e30f;
        }

        // Online softmax (row reduction across the 16 tx-lanes; xor<=8 stays in-group)
        #pragma unroll
        for (int i = 0; i < 4; i++) {
            float mx = fmaxf(fmaxf(s[i][0], s[i][1]), fmaxf(s[i][2], s[i][3]));
            #pragma unroll
            for (int off = 8; off > 0; off >>= 1)
                mx = fmaxf(mx, __shfl_xor_sync(0xffffffffu, mx, off));
            float mnew = fmaxf(m_i[i], mx);
            float corr = __expf(fmaxf(m_i[i] - mnew, -80.f));
            m_i[i] = mnew;
            float rs = 0.f;
            #pragma unroll
            for (int j = 0; j < 4; j++) {
                float p = __expf(fmaxf(s[i][j] - mnew, -80.f));
                s[i][j] = p; rs += p;
            }
            #pragma unroll
            for (int off = 8; off > 0; off >>= 1)
                rs += __shfl_xor_sync(0xffffffffu, rs, off);
            l_i[i] = l_i[i]*corr + rs;
            #pragma unroll
            for (int j = 0; j < 4; j++) o[i][j] *= corr;
        }

        __syncthreads();  // everyone done reading K from KPs
        // Stage P into KPs (swizzled per row)
        #pragma unroll
        for (int i = 0; i < 4; i++) {
            int r = ty*4 + i;
            #pragma unroll
            for (int j = 0; j < 4; j++)
                KPs[r*64 + ((tx*4 + j) ^ SWZP(r))] = s[i][j];
        }
        __syncthreads();

        // O += P @ V
        #pragma unroll 8
        for (int k = 0; k < 64; k++) {
            float4 vv = *(const float4*)&Vs[k*64 + (tx<<2)];
            #pragma unroll
            for (int i = 0; i < 4; i++) {
                int r = ty*4 + i;
                float p = KPs[r*64 + (k ^ SWZP(r))];
                o[i][0] = fmaf(p, vv.x, o[i][0]);
                o[i][1] = fmaf(p, vv.y, o[i][1]);
                o[i][2] = fmaf(p, vv.z, o[i][2]);
                o[i][3] = fmaf(p, vv.w, o[i][3]);
            }
        }
    }

    // Write context[b][s][h*64 + d]
    const int b = bh >> 3, h = bh & 7;
    #pragma unroll
    for (int i = 0; i < 4; i++) {
        int q = qt*64 + ty*4 + i;
        float inv = 1.f / l_i[i];
        float4 v = make_float4(o[i][0]*inv, o[i][1]*inv, o[i][2]*inv, o[i][3]*inv);
        *(float4*)&g_C[(size_t)(b*SS + q)*DD + h*DKK + (tx<<2)] = v;
    }
}

// ---------------------------------------------------------------------------
extern "C" void kernel_launch(void* const* d_in, const int* in_sizes, int n_in,
                              void* d_out, int out_size)
{
    const float* Xq = (const float*)d_in[0];
    const float* Xk = (const float*)d_in[1];
    const float* Xv = (const float*)d_in[2];
    const float* Wq = (const float*)d_in[3];
    const float* Wk = (const float*)d_in[4];
    const float* Wv = (const float*)d_in[5];
    const float* Wo = (const float*)d_in[6];
    float* out = (float*)d_out;

    dim3 ggrid(MM/128, DD/128);   // 64 x 4
    proj_gemm<<<ggrid, 256>>>(Xq, Wq, 0);
    proj_gemm<<<ggrid, 256>>>(Xk, Wk, 1);
    proj_gemm<<<ggrid, 256>>>(Xv, Wv, 2);

    attn_kernel<<<dim3(SS/64, BB*HH), 256>>>();   // 32 x 32

    out_gemm<<<ggrid, 256>>>(Wo, out);
}

// round 3
// speedup vs baseline: 1.1796x; 1.1796x over previous
#include <cuda_runtime.h>
#include <cstdint>

#define BB 4
#define SS 2048
#define DD 512
#define HH 8
#define DKK 64
#define MM (BB*SS)

// Scratch (__device__ globals: allocations are forbidden)
__device__ float g_Q[BB*HH*SS*DKK];   // [B,H,S,dk]
__device__ float g_K[BB*HH*SS*DKK];
__device__ float g_V[BB*HH*SS*DKK];
__device__ float g_C[BB*SS*DD];       // context [B,S,D]

// ---------------------------------------------------------------------------
// mma.sync tf32 helpers (compute_80 PTX — works on base sm_103 target)
// ---------------------------------------------------------------------------
__device__ __forceinline__ void mma_tf32(float* c, const uint32_t* a, const uint32_t* b) {
    asm volatile(
        "mma.sync.aligned.m16n8k8.row.col.f32.tf32.tf32.f32 "
        "{%0,%1,%2,%3}, {%4,%5,%6,%7}, {%8,%9}, {%0,%1,%2,%3};"
        : "+f"(c[0]), "+f"(c[1]), "+f"(c[2]), "+f"(c[3])
        : "r"(a[0]), "r"(a[1]), "r"(a[2]), "r"(a[3]), "r"(b[0]), "r"(b[1]));
}

__device__ __forceinline__ void split_tf32(float x, float& hi, float& lo) {
    uint32_t u;
    asm("cvt.rna.tf32.f32 %0, %1;" : "=r"(u) : "f"(x));
    hi = __uint_as_float(u);
    float r = x - hi;
    uint32_t v;
    asm("cvt.rna.tf32.f32 %0, %1;" : "=r"(v) : "f"(r));
    lo = __uint_as_float(v);
}

// ---------------------------------------------------------------------------
// tf32-split GEMM (NT): C[m,n] = sum_k A[m,k] * W[n,k].  M=8192, N=512, K=512.
// 128x128 block tile, BK=32, 256 threads (8 warps), warp tile 64x32.
// which: 0/1/2 -> permuted store to g_Q/g_K/g_V ; 3 -> plain store to out.
// ---------------------------------------------------------------------------
#define PADS 36                     // smem row stride in floats
#define PLANE (128*PADS)            // floats per plane
#define GSMEM (4*PLANE*4)           // bytes: Ahi, Alo, Bhi, Blo

__global__ __launch_bounds__(256)
void gemm_mma(const float* __restrict__ A_in, const float* __restrict__ W,
              float* __restrict__ out_direct, int which)
{
    extern __shared__ float smf[];
    float* Ahi = smf;
    float* Alo = smf + PLANE;
    float* Bhi = smf + 2*PLANE;
    float* Blo = smf + 3*PLANE;

    const int tid = threadIdx.x;
    const int wid = tid >> 5;
    const int lid = tid & 31;
    const int gID = lid >> 2;          // 0..7
    const int tig = lid & 3;           // 0..3
    const int bm  = blockIdx.x * 128;
    const int bn  = blockIdx.y * 128;
    const int wm  = (wid & 1) * 64;    // warp m offset in tile
    const int wn  = (wid >> 1) * 32;   // warp n offset in tile

    const float* Ap = (which == 3) ? g_C : A_in;

    float acc[4][4][4];
    #pragma unroll
    for (int i = 0; i < 4; i++)
        #pragma unroll
        for (int j = 0; j < 4; j++)
            #pragma unroll
            for (int t = 0; t < 4; t++) acc[i][j][t] = 0.f;

    for (int c = 0; c < DD/32; c++) {
        const int k0 = c * 32;
        if (c) __syncthreads();   // consumers of previous chunk done
        // ---- stage chunk: global -> split -> smem ----
        #pragma unroll
        for (int q = 0; q < 4; q++) {
            int idx  = q * 256 + tid;      // float4 slot 0..1023
            int row  = idx >> 3;           // 0..127
            int c4   = (idx & 7) << 2;     // 0..28
            float4 a = *(const float4*)(Ap + (size_t)(bm + row) * DD + k0 + c4);
            float4 b = *(const float4*)(W  + (size_t)(bn + row) * DD + k0 + c4);
            float4 ah, al, bh, bl;
            split_tf32(a.x, ah.x, al.x); split_tf32(a.y, ah.y, al.y);
            split_tf32(a.z, ah.z, al.z); split_tf32(a.w, ah.w, al.w);
            split_tf32(b.x, bh.x, bl.x); split_tf32(b.y, bh.y, bl.y);
            split_tf32(b.z, bh.z, bl.z); split_tf32(b.w, bh.w, bl.w);
            int off = row * PADS + c4;
            *(float4*)&Ahi[off] = ah;
            *(float4*)&Alo[off] = al;
            *(float4*)&Bhi[off] = bh;
            *(float4*)&Blo[off] = bl;
        }
        __syncthreads();

        // ---- 4 k-steps of 8 ----
        #pragma unroll
        for (int ks = 0; ks < 4; ks++) {
            const int kk = ks * 8 + tig;
            uint32_t bhf[4][2], blf[4][2];
            #pragma unroll
            for (int ni = 0; ni < 4; ni++) {
                int n = wn + ni * 8 + gID;
                bhf[ni][0] = __float_as_uint(Bhi[n * PADS + kk]);
                bhf[ni][1] = __float_as_uint(Bhi[n * PADS + kk + 4]);
                blf[ni][0] = __float_as_uint(Blo[n * PADS + kk]);
                blf[ni][1] = __float_as_uint(Blo[n * PADS + kk + 4]);
            }
            #pragma unroll
            for (int mi = 0; mi < 4; mi++) {
                int m = wm + mi * 16 + gID;
                uint32_t ahf[4], alf[4];
                ahf[0] = __float_as_uint(Ahi[m * PADS + kk]);
                ahf[1] = __float_as_uint(Ahi[(m + 8) * PADS + kk]);
                ahf[2] = __float_as_uint(Ahi[m * PADS + kk + 4]);
                ahf[3] = __float_as_uint(Ahi[(m + 8) * PADS + kk + 4]);
                alf[0] = __float_as_uint(Alo[m * PADS + kk]);
                alf[1] = __float_as_uint(Alo[(m + 8) * PADS + kk]);
                alf[2] = __float_as_uint(Alo[m * PADS + kk + 4]);
                alf[3] = __float_as_uint(Alo[(m + 8) * PADS + kk + 4]);
                #pragma unroll
                for (int ni = 0; ni < 4; ni++) {
                    mma_tf32(acc[mi][ni], ahf, bhf[ni]);
                    mma_tf32(acc[mi][ni], ahf, blf[ni]);
                    mma_tf32(acc[mi][ni], alf, bhf[ni]);
                }
            }
        }
    }

    // ---- epilogue ----
    #pragma unroll
    for (int mi = 0; mi < 4; mi++) {
        int r0 = bm + wm + mi * 16 + gID;
        #pragma unroll
        for (int ni = 0; ni < 4; ni++) {
            int n = bn + wn + ni * 8 + 2 * tig;
            if (which < 3) {
                float* outp = (which == 0) ? g_Q : (which == 1) ? g_K : g_V;
                int h = n >> 6, dj = n & 63;
                int b0 = r0 >> 11, s0 = r0 & (SS - 1);
                float2 v0 = make_float2(acc[mi][ni][0], acc[mi][ni][1]);
                float2 v1 = make_float2(acc[mi][ni][2], acc[mi][ni][3]);
                *(float2*)&outp[((size_t)(b0 * HH + h) * SS + s0) * DKK + dj] = v0;
                int r1 = r0 + 8;
                int b1 = r1 >> 11, s1 = r1 & (SS - 1);
                *(float2*)&outp[((size_t)(b1 * HH + h) * SS + s1) * DKK + dj] = v1;
            } else {
                float2 v0 = make_float2(acc[mi][ni][0], acc[mi][ni][1]);
                float2 v1 = make_float2(acc[mi][ni][2], acc[mi][ni][3]);
                *(float2*)&out_direct[(size_t)r0 * DD + n] = v0;
                *(float2*)&out_direct[(size_t)(r0 + 8) * DD + n] = v1;
            }
        }
    }
}

// ---------------------------------------------------------------------------
// Causal flash attention (unchanged from R1): 64x64 tiles, 256 thr, 4x4 micro.
// ---------------------------------------------------------------------------
#define SWZK(d) ((((d) >> 2) & 15) << 2)
#define SWZP(r) (((r) & 15) << 2)

__global__ __launch_bounds__(256, 2)
void attn_kernel()
{
    __shared__ float Qs[64*64];
    __shared__ float KPs[64*64];
    __shared__ float Vs[64*64];

    const int tid = threadIdx.x;
    const int tx  = tid & 15;
    const int ty  = tid >> 4;

    const int qt = (int)gridDim.x - 1 - (int)blockIdx.x;
    const int bh = blockIdx.y;

    const float* Qg = g_Q + (size_t)bh * SS * DKK;
    const float* Kg = g_K + (size_t)bh * SS * DKK;
    const float* Vg = g_V + (size_t)bh * SS * DKK;

    #pragma unroll
    for (int it = 0; it < 4; it++) {
        int idx = it*256 + tid;
        int r   = idx >> 4;
        int c4  = (idx & 15) << 2;
        float4 v = *(const float4*)(Qg + (size_t)(qt*64 + r)*DKK + c4);
        v.x *= 0.125f; v.y *= 0.125f; v.z *= 0.125f; v.w *= 0.125f;
        *(float4*)&Qs[r*64 + c4] = v;
    }

    float m_i[4], l_i[4], o[4][4];
    #pragma unroll
    for (int i = 0; i < 4; i++) {
        m_i[i] = -1e30f; l_i[i] = 0.f;
        #pragma unroll
        for (int j = 0; j < 4; j++) o[i][j] = 0.f;
    }

    for (int kt = 0; kt <= qt; kt++) {
        __syncthreads();
        #pragma unroll
        for (int it = 0; it < 4; it++) {
            int idx = it*256 + tid;
            int r   = idx >> 4;
            int c4  = (idx & 15) << 2;
            float4 kv = *(const float4*)(Kg + (size_t)(kt*64 + r)*DKK + c4);
            KPs[(c4+0)*64 + (r ^ SWZK(c4+0))] = kv.x;
            KPs[(c4+1)*64 + (r ^ SWZK(c4+1))] = kv.y;
            KPs[(c4+2)*64 + (r ^ SWZK(c4+2))] = kv.z;
            KPs[(c4+3)*64 + (r ^ SWZK(c4+3))] = kv.w;
            float4 vv = *(const float4*)(Vg + (size_t)(kt*64 + r)*DKK + c4);
            *(float4*)&Vs[r*64 + c4] = vv;
        }
        __syncthreads();

        float s[4][4];
        #pragma unroll
        for (int i = 0; i < 4; i++)
            #pragma unroll
            for (int j = 0; j < 4; j++) s[i][j] = 0.f;

        #pragma unroll 8
        for (int d = 0; d < 64; d++) {
            float4 kv = *(const float4*)&KPs[d*64 + ((tx<<2) ^ SWZK(d))];
            #pragma unroll
            for (int i = 0; i < 4; i++) {
                float q = Qs[(ty*4+i)*64 + d];
                s[i][0] = fmaf(q, kv.x, s[i][0]);
                s[i][1] = fmaf(q, kv.y, s[i][1]);
                s[i][2] = fmaf(q, kv.z, s[i][2]);
                s[i][3] = fmaf(q, kv.w, s[i][3]);
            }
        }

        if (kt == qt) {
            #pragma unroll
            for (int i = 0; i < 4; i++)
                #pragma unroll
                for (int j = 0; j < 4; j++)
                    if (tx*4 + j > ty*4 + i) s[i][j] = -1e30f;
        }

        #pragma unroll
        for (int i = 0; i < 4; i++) {
            float mx = fmaxf(fmaxf(s[i][0], s[i][1]), fmaxf(s[i][2], s[i][3]));
            #pragma unroll
            for (int off = 8; off > 0; off >>= 1)
                mx = fmaxf(mx, __shfl_xor_sync(0xffffffffu, mx, off));
            float mnew = fmaxf(m_i[i], mx);
            float corr = __expf(fmaxf(m_i[i] - mnew, -80.f));
            m_i[i] = mnew;
            float rs = 0.f;
            #pragma unroll
            for (int j = 0; j < 4; j++) {
                float p = __expf(fmaxf(s[i][j] - mnew, -80.f));
                s[i][j] = p; rs += p;
            }
            #pragma unroll
            for (int off = 8; off > 0; off >>= 1)
                rs += __shfl_xor_sync(0xffffffffu, rs, off);
            l_i[i] = l_i[i]*corr + rs;
            #pragma unroll
            for (int j = 0; j < 4; j++) o[i][j] *= corr;
        }

        __syncthreads();
        #pragma unroll
        for (int i = 0; i < 4; i++) {
            int r = ty*4 + i;
            #pragma unroll
            for (int j = 0; j < 4; j++)
                KPs[r*64 + ((tx*4 + j) ^ SWZP(r))] = s[i][j];
        }
        __syncthreads();

        #pragma unroll 8
        for (int k = 0; k < 64; k++) {
            float4 vv = *(const float4*)&Vs[k*64 + (tx<<2)];
            #pragma unroll
            for (int i = 0; i < 4; i++) {
                int r = ty*4 + i;
                float p = KPs[r*64 + (k ^ SWZP(r))];
                o[i][0] = fmaf(p, vv.x, o[i][0]);
                o[i][1] = fmaf(p, vv.y, o[i][1]);
                o[i][2] = fmaf(p, vv.z, o[i][2]);
                o[i][3] = fmaf(p, vv.w, o[i][3]);
            }
        }
    }

    const int b = bh >> 3, h = bh & 7;
    #pragma unroll
    for (int i = 0; i < 4; i++) {
        int q = qt*64 + ty*4 + i;
        float inv = 1.f / l_i[i];
        float4 v = make_float4(o[i][0]*inv, o[i][1]*inv, o[i][2]*inv, o[i][3]*inv);
        *(float4*)&g_C[(size_t)(b*SS + q)*DD + h*DKK + (tx<<2)] = v;
    }
}

// ---------------------------------------------------------------------------
extern "C" void kernel_launch(void* const* d_in, const int* in_sizes, int n_in,
                              void* d_out, int out_size)
{
    const float* Xq = (const float*)d_in[0];
    const float* Xk = (const float*)d_in[1];
    const float* Xv = (const float*)d_in[2];
    const float* Wq = (const float*)d_in[3];
    const float* Wk = (const float*)d_in[4];
    const float* Wv = (const float*)d_in[5];
    const float* Wo = (const float*)d_in[6];
    float* out = (float*)d_out;

    static bool attr_done = false;
    if (!attr_done) {
        cudaFuncSetAttribute(gemm_mma, cudaFuncAttributeMaxDynamicSharedMemorySize, GSMEM);
        attr_done = true;
    }

    dim3 ggrid(MM/128, DD/128);   // 64 x 4
    gemm_mma<<<ggrid, 256, GSMEM>>>(Xq, Wq, nullptr, 0);
    gemm_mma<<<ggrid, 256, GSMEM>>>(Xk, Wk, nullptr, 1);
    gemm_mma<<<ggrid, 256, GSMEM>>>(Xv, Wv, nullptr, 2);

    attn_kernel<<<dim3(SS/64, BB*HH), 256>>>();

    gemm_mma<<<ggrid, 256, GSMEM>>>(nullptr, Wo, out, 3);
}

// round 4
// speedup vs baseline: 3.1740x; 2.6906x over previous
#include <cuda_runtime.h>
#include <cstdint>

#define BB 4
#define SS 2048
#define DD 512
#define HH 8
#define DKK 64
#define MM (BB*SS)
#define NBH (BB*HH)

// Packed bf16x2 split planes (uint32 = 2 bf16 along last dim)
__device__ uint32_t g_Qh[NBH*SS*32], g_Ql[NBH*SS*32];   // [bh][s][d/2]
__device__ uint32_t g_Kh[NBH*SS*32], g_Kl[NBH*SS*32];   // [bh][s][d/2]
__device__ uint32_t g_Vh[NBH*DKK*(SS/2)], g_Vl[NBH*DKK*(SS/2)]; // [bh][d][s/2] (transposed)
__device__ float    g_C[BB*SS*DD];                      // context [B,S,D] fp32

// ---------------------------------------------------------------------------
// mma.sync bf16 m16n8k16 (compute_80 PTX — fine on base sm_103 target)
// ---------------------------------------------------------------------------
__device__ __forceinline__ void mma_bf16(float* c, const uint32_t* a, const uint32_t* b) {
    asm volatile(
        "mma.sync.aligned.m16n8k16.row.col.f32.bf16.bf16.f32 "
        "{%0,%1,%2,%3}, {%4,%5,%6,%7}, {%8,%9}, {%0,%1,%2,%3};"
        : "+f"(c[0]), "+f"(c[1]), "+f"(c[2]), "+f"(c[3])
        : "r"(a[0]), "r"(a[1]), "r"(a[2]), "r"(a[3]), "r"(b[0]), "r"(b[1]));
}

// Split (x0,x1) into bf16x2 hi + bf16x2 lo packs (lo halves carry x0).
__device__ __forceinline__ void pack_split(float x0, float x1, uint32_t& H, uint32_t& L) {
    uint32_t h;
    asm("cvt.rn.bf16x2.f32 %0, %1, %2;" : "=r"(h) : "f"(x1), "f"(x0));
    float h0 = __uint_as_float(h << 16);
    float h1 = __uint_as_float(h & 0xffff0000u);
    float r0 = x0 - h0, r1 = x1 - h1;
    uint32_t l;
    asm("cvt.rn.bf16x2.f32 %0, %1, %2;" : "=r"(l) : "f"(r1), "f"(r0));
    H = h; L = l;
}

// ---------------------------------------------------------------------------
// bf16-split GEMM (NT): C[m,n] = sum_k A[m,k]*W[n,k].
// 128x128 tile, BK=32, 8 warps, warp tile 64x32.
// which: 0=Q, 1=K (split bf16 [bh][s][d/2]), 2=Vt (split bf16 [bh][d][s/2],
//        launched with swapped operands, M=512,N=8192), 3=fp32 out from g_C.
// ---------------------------------------------------------------------------
#define ST4 20   // smem row stride in uint32 (16 data + 4 pad)

__global__ __launch_bounds__(256)
void gemm_mma(const float* __restrict__ A_in, const float* __restrict__ W,
              float* __restrict__ out_direct, int which)
{
    __shared__ uint32_t Ahi[128*ST4], Alo[128*ST4], Bhi[128*ST4], Blo[128*ST4];

    const int tid = threadIdx.x;
    const int wid = tid >> 5;
    const int lid = tid & 31;
    const int gID = lid >> 2;
    const int tig = lid & 3;
    const int bm  = blockIdx.x * 128;
    const int bn  = blockIdx.y * 128;
    const int wm  = (wid & 1) * 64;
    const int wn  = (wid >> 1) * 32;

    const float* Ap = (which == 3) ? g_C : A_in;

    float acc[4][4][4];
    #pragma unroll
    for (int i = 0; i < 4; i++)
        #pragma unroll
        for (int j = 0; j < 4; j++)
            #pragma unroll
            for (int t = 0; t < 4; t++) acc[i][j][t] = 0.f;

    for (int c = 0; c < DD/32; c++) {
        const int k0 = c * 32;
        if (c) __syncthreads();
        // ---- stage: global fp32 -> split bf16x2 -> smem ----
        #pragma unroll
        for (int q = 0; q < 4; q++) {
            int idx  = q * 256 + tid;
            int row  = idx >> 3;
            int j    = idx & 7;          // float4 within row (k = 4j..4j+3)
            float4 a = *(const float4*)(Ap + (size_t)(bm + row) * DD + k0 + 4*j);
            float4 b = *(const float4*)(W  + (size_t)(bn + row) * DD + k0 + 4*j);
            uint32_t h0,l0,h1,l1;
            pack_split(a.x, a.y, h0, l0); pack_split(a.z, a.w, h1, l1);
            int off = row * ST4 + 2*j;
            *(uint2*)&Ahi[off] = make_uint2(h0, h1);
            *(uint2*)&Alo[off] = make_uint2(l0, l1);
            pack_split(b.x, b.y, h0, l0); pack_split(b.z, b.w, h1, l1);
            *(uint2*)&Bhi[off] = make_uint2(h0, h1);
            *(uint2*)&Blo[off] = make_uint2(l0, l1);
        }
        __syncthreads();

        // ---- 2 k-steps of 16 ----
        #pragma unroll
        for (int ks = 0; ks < 2; ks++) {
            const int kp = 8*ks + tig;
            uint32_t bhf[4][2], blf[4][2];
            #pragma unroll
            for (int ni = 0; ni < 4; ni++) {
                int n = wn + ni*8 + gID;
                bhf[ni][0] = Bhi[n*ST4 + kp];  bhf[ni][1] = Bhi[n*ST4 + kp + 4];
                blf[ni][0] = Blo[n*ST4 + kp];  blf[ni][1] = Blo[n*ST4 + kp + 4];
            }
            #pragma unroll
            for (int mi = 0; mi < 4; mi++) {
                int m = wm + mi*16 + gID;
                uint32_t ahf[4], alf[4];
                ahf[0] = Ahi[m*ST4 + kp];       ahf[1] = Ahi[(m+8)*ST4 + kp];
                ahf[2] = Ahi[m*ST4 + kp + 4];   ahf[3] = Ahi[(m+8)*ST4 + kp + 4];
                alf[0] = Alo[m*ST4 + kp];       alf[1] = Alo[(m+8)*ST4 + kp];
                alf[2] = Alo[m*ST4 + kp + 4];   alf[3] = Alo[(m+8)*ST4 + kp + 4];
                #pragma unroll
                for (int ni = 0; ni < 4; ni++) {
                    mma_bf16(acc[mi][ni], ahf, bhf[ni]);
                    mma_bf16(acc[mi][ni], ahf, blf[ni]);
                    mma_bf16(acc[mi][ni], alf, bhf[ni]);
                }
            }
        }
    }

    // ---- epilogue ----
    #pragma unroll
    for (int mi = 0; mi < 4; mi++) {
        int rm = bm + wm + mi*16 + gID;
        #pragma unroll
        for (int ni = 0; ni < 4; ni++) {
            int n = bn + wn + ni*8 + 2*tig;
            float* a = acc[mi][ni];
            if (which <= 1) {
                // Q/K: split bf16 planes [bh][s][d/2]
                uint32_t* Hp = (which == 0) ? g_Qh : g_Kh;
                uint32_t* Lp = (which == 0) ? g_Ql : g_Kl;
                int h = n >> 6, dp = (n & 63) >> 1;
                int b0 = rm >> 11, s0 = rm & (SS-1);
                uint32_t H, L;
                pack_split(a[0], a[1], H, L);
                size_t o0 = ((size_t)(b0*HH + h)*SS + s0)*32 + dp;
                Hp[o0] = H; Lp[o0] = L;
                pack_split(a[2], a[3], H, L);
                int r1 = rm + 8;
                size_t o1 = ((size_t)((r1>>11)*HH + h)*SS + (r1 & (SS-1)))*32 + dp;
                Hp[o1] = H; Lp[o1] = L;
            } else if (which == 2) {
                // Vt: m = global d-row, n = global s.  Pairs along s.
                int h = rm >> 6, dj = rm & 63;
                int b = n >> 11, sl = n & (SS-1);
                uint32_t H, L;
                pack_split(a[0], a[1], H, L);
                size_t o0 = ((size_t)(b*HH + h)*DKK + dj)*(SS/2) + (sl >> 1);
                g_Vh[o0] = H; g_Vl[o0] = L;
                pack_split(a[2], a[3], H, L);
                size_t o1 = ((size_t)(b*HH + h)*DKK + dj + 8)*(SS/2) + (sl >> 1);
                g_Vh[o1] = H; g_Vl[o1] = L;
            } else {
                *(float2*)&out_direct[(size_t)rm*DD + n]     = make_float2(a[0], a[1]);
                *(float2*)&out_direct[(size_t)(rm+8)*DD + n] = make_float2(a[2], a[3]);
            }
        }
    }
}

// ---------------------------------------------------------------------------
// bf16-split flash attention (causal).  64 q-rows/block, 4 warps (16 rows each).
// S = QK^T via 3-term bf16 mma; fragment-space softmax; P->A frag direct; PV split.
// ---------------------------------------------------------------------------
#define AST 36   // attn smem row stride in uint32 (32 data + 4 pad)

__global__ __launch_bounds__(128)
void attn_mma()
{
    __shared__ uint32_t sKh[64*AST], sKl[64*AST], sVh[64*AST], sVl[64*AST];

    const int tid = threadIdx.x;
    const int w   = tid >> 5;
    const int lid = tid & 31;
    const int gID = lid >> 2;
    const int tig = lid & 3;

    const int qt = (int)gridDim.x - 1 - (int)blockIdx.x;  // long rows first
    const int bh = blockIdx.y;

    const int q0l = w*16 + gID;          // local row (0..63), second row +8
    const int q0  = qt*64 + q0l;

    // ---- Q fragments (hi/lo), resident for the whole block ----
    uint32_t qh[4][4], ql[4][4];
    {
        const uint32_t* Qhp = g_Qh + ((size_t)bh*SS + q0)*32;
        const uint32_t* Qlp = g_Ql + ((size_t)bh*SS + q0)*32;
        #pragma unroll
        for (int ks = 0; ks < 4; ks++) {
            int p = 8*ks + tig;
            qh[ks][0] = Qhp[p];          qh[ks][1] = Qhp[8*32 + p];
            qh[ks][2] = Qhp[p + 4];      qh[ks][3] = Qhp[8*32 + p + 4];
            ql[ks][0] = Qlp[p];          ql[ks][1] = Qlp[8*32 + p];
            ql[ks][2] = Qlp[p + 4];      ql[ks][3] = Qlp[8*32 + p + 4];
        }
    }

    float m0 = -1e30f, m1 = -1e30f, l0 = 0.f, l1 = 0.f;
    float accO[8][4];
    #pragma unroll
    for (int nt = 0; nt < 8; nt++)
        #pragma unroll
        for (int t = 0; t < 4; t++) accO[nt][t] = 0.f;

    for (int kt = 0; kt <= qt; kt++) {
        __syncthreads();   // previous tile's LDS consumers done
        // ---- load K (row-major [kcol][d/2]) and Vt ([d][s/2]) hi/lo tiles ----
        #pragma unroll
        for (int it = 0; it < 4; it++) {
            int idx = it*128 + tid;
            int r   = idx >> 3;
            int c4  = (idx & 7) << 2;
            size_t ko = ((size_t)bh*SS + kt*64 + r)*32 + c4;
            *(int4*)&sKh[r*AST + c4] = *(const int4*)&g_Kh[ko];
            *(int4*)&sKl[r*AST + c4] = *(const int4*)&g_Kl[ko];
            size_t vo = ((size_t)bh*DKK + r)*(SS/2) + kt*32 + c4;
            *(int4*)&sVh[r*AST + c4] = *(const int4*)&g_Vh[vo];
            *(int4*)&sVl[r*AST + c4] = *(const int4*)&g_Vl[vo];
        }
        __syncthreads();

        // ---- S = Q K^T (3-term split) ----
        float accS[8][4];
        #pragma unroll
        for (int nt = 0; nt < 8; nt++)
            #pragma unroll
            for (int t = 0; t < 4; t++) accS[nt][t] = 0.f;

        #pragma unroll
        for (int ks = 0; ks < 4; ks++) {
            const int kp = 8*ks + tig;
            #pragma unroll
            for (int nt = 0; nt < 8; nt++) {
                int row = (nt*8 + gID) * AST;
                uint32_t bh_[2] = { sKh[row + kp], sKh[row + kp + 4] };
                uint32_t bl_[2] = { sKl[row + kp], sKl[row + kp + 4] };
                mma_bf16(accS[nt], qh[ks], bh_);
                mma_bf16(accS[nt], qh[ks], bl_);
                mma_bf16(accS[nt], ql[ks], bh_);
            }
        }

        // ---- scale + causal mask ----
        #pragma unroll
        for (int nt = 0; nt < 8; nt++)
            #pragma unroll
            for (int t = 0; t < 4; t++) accS[nt][t] *= 0.125f;
        if (kt == qt) {
            #pragma unroll
            for (int nt = 0; nt < 8; nt++) {
                int c0 = nt*8 + 2*tig;
                if (c0     > q0l) accS[nt][0] = -1e30f;
                if (c0 + 1 > q0l) accS[nt][1] = -1e30f;
                if (c0     > q0l + 8) accS[nt][2] = -1e30f;
                if (c0 + 1 > q0l + 8) accS[nt][3] = -1e30f;
            }
        }

        // ---- online softmax (rows r0 = c0/c1, r1 = c2/c3) ----
        float mx0 = -1e30f, mx1 = -1e30f;
        #pragma unroll
        for (int nt = 0; nt < 8; nt++) {
            mx0 = fmaxf(mx0, fmaxf(accS[nt][0], accS[nt][1]));
            mx1 = fmaxf(mx1, fmaxf(accS[nt][2], accS[nt][3]));
        }
        #pragma unroll
        for (int off = 1; off <= 2; off <<= 1) {
            mx0 = fmaxf(mx0, __shfl_xor_sync(0xffffffffu, mx0, off));
            mx1 = fmaxf(mx1, __shfl_xor_sync(0xffffffffu, mx1, off));
        }
        float mn0 = fmaxf(m0, mx0), mn1 = fmaxf(m1, mx1);
        float corr0 = __expf(m0 - mn0), corr1 = __expf(m1 - mn1);
        m0 = mn0; m1 = mn1;

        float sum0 = 0.f, sum1 = 0.f;
        #pragma unroll
        for (int nt = 0; nt < 8; nt++) {
            accS[nt][0] = __expf(accS[nt][0] - mn0);
            accS[nt][1] = __expf(accS[nt][1] - mn0);
            accS[nt][2] = __expf(accS[nt][2] - mn1);
            accS[nt][3] = __expf(accS[nt][3] - mn1);
            sum0 += accS[nt][0] + accS[nt][1];
            sum1 += accS[nt][2] + accS[nt][3];
        }
        #pragma unroll
        for (int off = 1; off <= 2; off <<= 1) {
            sum0 += __shfl_xor_sync(0xffffffffu, sum0, off);
            sum1 += __shfl_xor_sync(0xffffffffu, sum1, off);
        }
        l0 = l0*corr0 + sum0;
        l1 = l1*corr1 + sum1;
        #pragma unroll
        for (int nt = 0; nt < 8; nt++) {
            accO[nt][0] *= corr0; accO[nt][1] *= corr0;
            accO[nt][2] *= corr1; accO[nt][3] *= corr1;
        }

        // ---- P -> bf16 split A-fragments (register-only remap) ----
        uint32_t ph[4][4], pl[4][4];
        #pragma unroll
        for (int ks = 0; ks < 4; ks++) {
            pack_split(accS[2*ks  ][0], accS[2*ks  ][1], ph[ks][0], pl[ks][0]);
            pack_split(accS[2*ks  ][2], accS[2*ks  ][3], ph[ks][1], pl[ks][1]);
            pack_split(accS[2*ks+1][0], accS[2*ks+1][1], ph[ks][2], pl[ks][2]);
            pack_split(accS[2*ks+1][2], accS[2*ks+1][3], ph[ks][3], pl[ks][3]);
        }

        // ---- O += P V (3-term split) ----
        #pragma unroll
        for (int ks = 0; ks < 4; ks++) {
            const int kp = 8*ks + tig;
            #pragma unroll
            for (int nt = 0; nt < 8; nt++) {
                int row = (nt*8 + gID) * AST;
                uint32_t bh_[2] = { sVh[row + kp], sVh[row + kp + 4] };
                uint32_t bl_[2] = { sVl[row + kp], sVl[row + kp + 4] };
                mma_bf16(accO[nt], ph[ks], bh_);
                mma_bf16(accO[nt], ph[ks], bl_);
                mma_bf16(accO[nt], pl[ks], bh_);
            }
        }
    }

    // ---- epilogue: context[b][s][h*64+d] ----
    const int b = bh >> 3, h = bh & 7;
    const float inv0 = 1.f / l0, inv1 = 1.f / l1;
    #pragma unroll
    for (int nt = 0; nt < 8; nt++) {
        int d = h*64 + nt*8 + 2*tig;
        *(float2*)&g_C[((size_t)b*SS + q0)*DD + d] =
            make_float2(accO[nt][0]*inv0, accO[nt][1]*inv0);
        *(float2*)&g_C[((size_t)b*SS + q0 + 8)*DD + d] =
            make_float2(accO[nt][2]*inv1, accO[nt][3]*inv1);
    }
}

// ---------------------------------------------------------------------------
extern "C" void kernel_launch(void* const* d_in, const int* in_sizes, int n_in,
                              void* d_out, int out_size)
{
    const float* Xq = (const float*)d_in[0];
    const float* Xk = (const float*)d_in[1];
    const float* Xv = (const float*)d_in[2];
    const float* Wq = (const float*)d_in[3];
    const float* Wk = (const float*)d_in[4];
    const float* Wv = (const float*)d_in[5];
    const float* Wo = (const float*)d_in[6];
    float* out = (float*)d_out;

    dim3 gqk(MM/128, DD/128);     // 64 x 4
    gemm_mma<<<gqk, 256>>>(Xq, Wq, nullptr, 0);
    gemm_mma<<<gqk, 256>>>(Xk, Wk, nullptr, 1);
    gemm_mma<<<dim3(DD/128, MM/128), 256>>>(Wv, Xv, nullptr, 2);   // Vt = Wv @ Xv^T

    attn_mma<<<dim3(SS/64, NBH), 128>>>();                         // 32 x 32

    gemm_mma<<<gqk, 256>>>(nullptr, Wo, out, 3);
}